// round 13
// baseline (speedup 1.0000x reference)
#include <cuda_runtime.h>

// chamfer_3DDist: B=16, N=M=4096.
// Output (float32): [dist1 (B*N) | dist2 (B*M) | idx1 (B*N) | idx2 (B*M)]
//
// Round-13: (1) main kernel: 128-reg budget + front-batched preload of the
// whole k8-unit's candidate data (16-deep LDS MLP) to close the issue gap;
// (2) single fused finalize: per-block cooperative COALESCED partial load to
// smem, then warp-per-element butterfly merge + bit-identical rescan.
// All distances / tie-break orders bit-identical to the reference.

#define BT    64
#define UQ    4
#define QT    256            // queries per block (BT*UQ)
#define CT    256            // candidates per block
#define NPTS  4096
#define BATCH 16
#define NQB   (NPTS / QT)    // 16
#define NCB   (NPTS / CT)    // 16
#define GRPC  16             // row-deferral group (cands)
#define QRNG  64             // queries per col partial
#define NPART (NPTS / QRNG)  // 64 col partials per batch
#define FLTMAX 3.402823466e38f

typedef unsigned long long u64;

// row partials per cand-block: (best value, group index as float)
__device__ float2 g_row[NCB][BATCH * NPTS];
// col partials: partial p covers queries [p*64, p*64+64) within the batch
__device__ float  g_col[NPART][BATCH * NPTS];

__device__ __forceinline__ u64 pack2(float lo, float hi) {
    u64 r; asm("mov.b64 %0, {%1, %2};" : "=l"(r) : "f"(lo), "f"(hi)); return r;
}
__device__ __forceinline__ void unpack2(u64 v, float& lo, float& hi) {
    asm("mov.b64 {%0, %1}, %2;" : "=f"(lo), "=f"(hi) : "l"(v));
}
__device__ __forceinline__ u64 fma2(u64 a, u64 b, u64 c) {
    u64 d; asm("fma.rn.f32x2 %0, %1, %2, %3;" : "=l"(d) : "l"(a), "l"(b), "l"(c)); return d;
}
__device__ __forceinline__ u64 mul2(u64 a, u64 b) {
    u64 d; asm("mul.rn.f32x2 %0, %1, %2;" : "=l"(d) : "l"(a), "l"(b)); return d;
}
__device__ __forceinline__ u64 add2(u64 a, u64 b) {
    u64 d; asm("add.rn.f32x2 %0, %1, %2;" : "=l"(d) : "l"(a), "l"(b)); return d;
}

__device__ __forceinline__ float sqnorm_ref(float x, float y, float z) {
    return __fadd_rn(__fadd_rn(__fmul_rn(x, x), __fmul_rn(y, y)), __fmul_rn(z, z));
}
__device__ __forceinline__ float dist_ref(float qx, float qy, float qz, float q2,
                                          float cx, float cy, float cz, float c2) {
    float xy = __fmaf_rn(qz, cz, __fmaf_rn(qy, cy, __fmul_rn(qx, cx)));
    return __fmaf_rn(-2.0f, xy, __fadd_rn(q2, c2));
}

__global__ __launch_bounds__(BT, 8) void nn_main(
    const float* __restrict__ xyz1,
    const float* __restrict__ xyz2)
{
    const int cblk = blockIdx.x, qblk = blockIdx.y, b = blockIdx.z;
    const int tid = threadIdx.x, w = tid >> 5, lane = tid & 31;

    __shared__ float4 sc[CT / 2][2];
    __shared__ u64 colpart[2][8][33];
    __shared__ float2 rowst[QT];

    // stage candidates (xyz2), scaled by -2; norms from UNSCALED coords
    const float* cbase = xyz2 + (size_t)(b * NPTS + cblk * CT) * 3;
    for (int pp = tid; pp < CT / 2; pp += BT) {
        const float* p0 = cbase + 6 * pp;
        const float a0 = p0[0], a1 = p0[1], a2 = p0[2];
        const float b0 = p0[3], b1 = p0[4], b2 = p0[5];
        const float w0 = sqnorm_ref(a0, a1, a2);
        const float w1 = sqnorm_ref(b0, b1, b2);
        sc[pp][0] = make_float4(-2.0f * a0, -2.0f * b0, -2.0f * a1, -2.0f * b1);
        sc[pp][1] = make_float4(-2.0f * a2, -2.0f * b2, w0, w1);
    }

    // queries: thread owns 4 CONSECUTIVE queries (12 contiguous floats)
    u64 qx2[UQ], qy2[UQ], qz2[UQ], q22[UQ];
    float best[UQ], gacc[UQ], jgrp[UQ];
    {
        const int q0 = b * NPTS + qblk * QT + tid * UQ;
        const float4* qv = (const float4*)(xyz1 + 3 * q0);
        const float4 v0 = qv[0], v1 = qv[1], v2 = qv[2];
        const float qs[UQ][3] = {{v0.x, v0.y, v0.z}, {v0.w, v1.x, v1.y},
                                 {v1.z, v1.w, v2.x}, {v2.y, v2.z, v2.w}};
#pragma unroll
        for (int u = 0; u < UQ; ++u) {
            const float x0 = qs[u][0], x1 = qs[u][1], x2v = qs[u][2];
            const float s = sqnorm_ref(x0, x1, x2v);
            qx2[u] = pack2(x0, x0);
            qy2[u] = pack2(x1, x1);
            qz2[u] = pack2(x2v, x2v);
            q22[u] = pack2(s, s);
            best[u] = FLTMAX;
            gacc[u] = FLTMAX;
            jgrp[u] = 0.0f;
        }
    }
    __syncthreads();

    const ulonglong2* __restrict__ sp = (const ulonglong2*)sc;
    const int cand0 = b * NPTS + cblk * CT;

    for (int k8 = 0; k8 < CT / 2; k8 += 8) {
        // front-batch ALL candidate data for this unit (16 LDS.128 in flight)
        ulonglong2 c[16];
#pragma unroll
        for (int i = 0; i < 16; ++i) c[i] = sp[2 * k8 + i];

#pragma unroll
        for (int j = 0; j < 8; ++j) {
            const ulonglong2 A  = c[2 * j];      // (-2X pair, -2Y pair)
            const ulonglong2 Bv = c[2 * j + 1];  // (-2Z pair,  W pair)
            float cl, ch;
#pragma unroll
            for (int u = 0; u < UQ; ++u) {
                u64 t = fma2(qz2[u], Bv.x, fma2(qy2[u], A.y, mul2(qx2[u], A.x)));
                u64 d = add2(t, add2(q22[u], Bv.y));   // == fma(-2,xy,q2+c2)
                float dlo, dhi; unpack2(d, dlo, dhi);
                gacc[u] = fminf(gacc[u], fminf(dlo, dhi));
                if (u == 0) { cl = dlo; ch = dhi; }
                else        { cl = fminf(cl, dlo); ch = fminf(ch, dhi); }
            }
            colpart[w][j][lane] = pack2(cl, ch);
        }

        // row group commit (16 cands/group), ascending -> strict <
        const float gidx = (float)(cblk * (CT / GRPC) + (k8 >> 3));
#pragma unroll
        for (int u = 0; u < UQ; ++u) {
            jgrp[u] = (gacc[u] < best[u]) ? gidx : jgrp[u];
            best[u] = fminf(best[u], gacc[u]);
            gacc[u] = FLTMAX;
        }

        // col flush: 32 reductions (8 pairs x 2 query-halves x 2 cands);
        // each 64-query half stored as its own partial (ascending ranges)
        __syncwarp();
        {
            const int p = lane >> 2;          // pair 0..7
            const int s = (lane >> 1) & 1;    // query half (64 queries)
            const int h = lane & 1;           // lo/hi cand of the pair
            const float* fb = (const float*)colpart[w][p];
            float v = fb[(s * 16) * 2 + h];
#pragma unroll
            for (int i = 1; i < 16; ++i)
                v = fminf(v, fb[(s * 16 + i) * 2 + h]);
            g_col[qblk * 4 + w * 2 + s][cand0 + 2 * (k8 + p) + h] = v;
        }
        __syncwarp();
    }

    // row epilogue: stage to smem, write coalesced
#pragma unroll
    for (int u = 0; u < UQ; ++u)
        rowst[tid * UQ + u] = make_float2(best[u], jgrp[u]);
    __syncthreads();
    {
        const int base = b * NPTS + qblk * QT;
        float2* __restrict__ gr = &g_row[cblk][base];
        for (int i = tid; i < QT; i += BT) gr[i] = rowst[i];
    }
}

// Fused finalize: each 256-thread block owns 8 same-kind elements.
// Phase 1: cooperative COALESCED load of all partials into smem.
// Phase 2: warp e merges element e's partials (earliest tying partial wins)
// and rescans bit-identically, taking the LOWEST matching global index.
__global__ __launch_bounds__(256) void nn_finalize(
    const float* __restrict__ xyz1,
    const float* __restrict__ xyz2,
    float* __restrict__ out)
{
    const int BN  = BATCH * NPTS;
    const int NRB = BN / 8;                 // row blocks
    const int tid = threadIdx.x;
    const int wid = tid >> 5, lane = tid & 31;

    __shared__ float2 srow[8][16];
    __shared__ float  scol[8][64];

    if (blockIdx.x < NRB) {
        // ======== rows: dist1/idx1 for queries qg0..qg0+7 ========
        const int qg0 = blockIdx.x * 8;

        if (tid < 128) {                     // (cb, e): coalesced 64B per cb
            const int cb = tid >> 3, e = tid & 7;
            srow[e][cb] = g_row[cb][qg0 + e];
        }
        __syncthreads();

        const int qg = qg0 + wid;
        const int b  = qg >> 12;

        float v = FLTMAX, g = 0.0f;
        int   p = 1 << 20;
        if (lane < NCB) {
            const float2 r = srow[wid][lane];
            v = r.x; g = r.y; p = lane;
        }
#pragma unroll
        for (int off = 16; off >= 1; off >>= 1) {
            const float ov = __shfl_xor_sync(0xffffffffu, v, off);
            const float og = __shfl_xor_sync(0xffffffffu, g, off);
            const int   op = __shfl_xor_sync(0xffffffffu, p, off);
            const bool tk = (ov < v) || (ov == v && op < p);
            v = tk ? ov : v; g = tk ? og : g; p = tk ? op : p;
        }
        const float bv = v;
        const int base = (int)g * GRPC;

        const float* qp = xyz1 + 3 * qg;
        const float qx = qp[0], qy = qp[1], qz = qp[2];
        const float q2 = sqnorm_ref(qx, qy, qz);

        int found = 0x7fffffff;
        if (lane < GRPC) {
            const float* cp = xyz2 + (size_t)b * NPTS * 3 + 3 * (base + lane);
            const float c2 = sqnorm_ref(cp[0], cp[1], cp[2]);
            const float d = dist_ref(qx, qy, qz, q2, cp[0], cp[1], cp[2], c2);
            if (d == bv) found = base + lane;
        }
#pragma unroll
        for (int off = 16; off >= 1; off >>= 1)
            found = min(found, __shfl_xor_sync(0xffffffffu, found, off));

        if (lane == 0) {
            out[qg]          = bv;
            out[2 * BN + qg] = (float)found;
        }
    } else {
        // ======== cols: dist2/idx2 for candidates mg0..mg0+7 ========
        const int mg0 = (blockIdx.x - NRB) * 8;

        {                                    // (p, e): coalesced 32B per p
            const int p = tid >> 3, e = tid & 7;
            scol[e][p]      = g_col[p][mg0 + e];
            scol[e][p + 32] = g_col[p + 32][mg0 + e];
        }
        __syncthreads();

        const int mg = mg0 + wid;
        const int b  = mg >> 12;

        // pre-merge the two halves (lower partial index wins ties)
        const float va = scol[wid][lane];
        const float vb = scol[wid][lane + 32];
        float v = (vb < va) ? vb : va;
        int   p = (vb < va) ? (lane + 32) : lane;
#pragma unroll
        for (int off = 16; off >= 1; off >>= 1) {
            const float ov = __shfl_xor_sync(0xffffffffu, v, off);
            const int   op = __shfl_xor_sync(0xffffffffu, p, off);
            const bool tk = (ov < v) || (ov == v && op < p);
            v = tk ? ov : v; p = tk ? op : p;
        }
        const float bv = v;
        const int   bp = p;                  // queries [bp*64, bp*64+64)

        const float* cp = xyz2 + 3 * mg;
        const float cx = cp[0], cy = cp[1], cz = cp[2];
        const float c2 = sqnorm_ref(cx, cy, cz);

        // rescan: lane l -> queries bp*64 + 2l + {0,1}, coalesced float2
        const int qn0 = b * NPTS + bp * QRNG + lane * 2;
        const float2* qv = (const float2*)(xyz1 + 3 * qn0);
        const float2 v0 = qv[0], v1 = qv[1], v2 = qv[2];
        const float qs[2][3] = {{v0.x, v0.y, v1.x}, {v1.y, v2.x, v2.y}};
        int found = 0x7fffffff;
#pragma unroll
        for (int k = 1; k >= 0; --k) {
            const float q2n = sqnorm_ref(qs[k][0], qs[k][1], qs[k][2]);
            const float d = dist_ref(qs[k][0], qs[k][1], qs[k][2], q2n,
                                     cx, cy, cz, c2);
            if (d == bv) found = bp * QRNG + lane * 2 + k;
        }
#pragma unroll
        for (int off = 16; off >= 1; off >>= 1)
            found = min(found, __shfl_xor_sync(0xffffffffu, found, off));

        if (lane == 0) {
            out[BN + mg]     = bv;
            out[3 * BN + mg] = (float)found;
        }
    }
}

extern "C" void kernel_launch(void* const* d_in, const int* in_sizes, int n_in,
                              void* d_out, int out_size)
{
    (void)in_sizes; (void)n_in; (void)out_size;
    const float* xyz1 = (const float*)d_in[0];
    const float* xyz2 = (const float*)d_in[1];
    float* out = (float*)d_out;

    dim3 grid(NCB, NQB, BATCH);   // (16, 16, 16) = 4096 blocks
    nn_main<<<grid, BT>>>(xyz1, xyz2);

    const int BN = BATCH * NPTS;
    nn_finalize<<<(2 * BN) / 8, 256>>>(xyz1, xyz2, out);
}

// round 14
// speedup vs baseline: 1.1024x; 1.1024x over previous
#include <cuda_runtime.h>

// chamfer_3DDist: B=16, N=M=4096.
// Output (float32): [dist1 (B*N) | dist2 (B*M) | idx1 (B*N) | idx2 (B*M)]
//
// Round-14: recombination of measured winners.
//  - main: R13 variant (front-batched 16-deep LDS preload, 128-reg budget) —
//    measured ~57us vs 62.6us for R12's.
//  - finalize: R12 variant (thread-per-element coalesced merge + warp-per-
//    element rescan, two launches) — measured 18.9us vs 31.5us fused.
// All distances / tie-break orders bit-identical to the reference.

#define BT    64
#define UQ    4
#define QT    256            // queries per block (BT*UQ)
#define CT    256            // candidates per block
#define NPTS  4096
#define BATCH 16
#define NQB   (NPTS / QT)    // 16
#define NCB   (NPTS / CT)    // 16
#define GRPC  16             // row-deferral group (cands)
#define QRNG  64             // queries per col partial
#define NPART (NPTS / QRNG)  // 64 col partials per batch
#define FLTMAX 3.402823466e38f

typedef unsigned long long u64;

// row partials per cand-block: (best value, group index as float)
__device__ float2 g_row[NCB][BATCH * NPTS];
// col partials: partial p covers queries [p*64, p*64+64) within the batch
__device__ float  g_col[NPART][BATCH * NPTS];
// merge selections: [0]=row winning group, [1]=col winning partial
__device__ int    g_sel[2][BATCH * NPTS];

__device__ __forceinline__ u64 pack2(float lo, float hi) {
    u64 r; asm("mov.b64 %0, {%1, %2};" : "=l"(r) : "f"(lo), "f"(hi)); return r;
}
__device__ __forceinline__ void unpack2(u64 v, float& lo, float& hi) {
    asm("mov.b64 {%0, %1}, %2;" : "=f"(lo), "=f"(hi) : "l"(v));
}
__device__ __forceinline__ u64 fma2(u64 a, u64 b, u64 c) {
    u64 d; asm("fma.rn.f32x2 %0, %1, %2, %3;" : "=l"(d) : "l"(a), "l"(b), "l"(c)); return d;
}
__device__ __forceinline__ u64 mul2(u64 a, u64 b) {
    u64 d; asm("mul.rn.f32x2 %0, %1, %2;" : "=l"(d) : "l"(a), "l"(b)); return d;
}
__device__ __forceinline__ u64 add2(u64 a, u64 b) {
    u64 d; asm("add.rn.f32x2 %0, %1, %2;" : "=l"(d) : "l"(a), "l"(b)); return d;
}

__device__ __forceinline__ float sqnorm_ref(float x, float y, float z) {
    return __fadd_rn(__fadd_rn(__fmul_rn(x, x), __fmul_rn(y, y)), __fmul_rn(z, z));
}
__device__ __forceinline__ float dist_ref(float qx, float qy, float qz, float q2,
                                          float cx, float cy, float cz, float c2) {
    float xy = __fmaf_rn(qz, cz, __fmaf_rn(qy, cy, __fmul_rn(qx, cx)));
    return __fmaf_rn(-2.0f, xy, __fadd_rn(q2, c2));
}

__global__ __launch_bounds__(BT, 8) void nn_main(
    const float* __restrict__ xyz1,
    const float* __restrict__ xyz2)
{
    const int cblk = blockIdx.x, qblk = blockIdx.y, b = blockIdx.z;
    const int tid = threadIdx.x, w = tid >> 5, lane = tid & 31;

    __shared__ float4 sc[CT / 2][2];
    __shared__ u64 colpart[2][8][33];
    __shared__ float2 rowst[QT];

    // stage candidates (xyz2), scaled by -2; norms from UNSCALED coords
    const float* cbase = xyz2 + (size_t)(b * NPTS + cblk * CT) * 3;
    for (int pp = tid; pp < CT / 2; pp += BT) {
        const float* p0 = cbase + 6 * pp;
        const float a0 = p0[0], a1 = p0[1], a2 = p0[2];
        const float b0 = p0[3], b1 = p0[4], b2 = p0[5];
        const float w0 = sqnorm_ref(a0, a1, a2);
        const float w1 = sqnorm_ref(b0, b1, b2);
        sc[pp][0] = make_float4(-2.0f * a0, -2.0f * b0, -2.0f * a1, -2.0f * b1);
        sc[pp][1] = make_float4(-2.0f * a2, -2.0f * b2, w0, w1);
    }

    // queries: thread owns 4 CONSECUTIVE queries (12 contiguous floats)
    u64 qx2[UQ], qy2[UQ], qz2[UQ], q22[UQ];
    float best[UQ], gacc[UQ], jgrp[UQ];
    {
        const int q0 = b * NPTS + qblk * QT + tid * UQ;
        const float4* qv = (const float4*)(xyz1 + 3 * q0);
        const float4 v0 = qv[0], v1 = qv[1], v2 = qv[2];
        const float qs[UQ][3] = {{v0.x, v0.y, v0.z}, {v0.w, v1.x, v1.y},
                                 {v1.z, v1.w, v2.x}, {v2.y, v2.z, v2.w}};
#pragma unroll
        for (int u = 0; u < UQ; ++u) {
            const float x0 = qs[u][0], x1 = qs[u][1], x2v = qs[u][2];
            const float s = sqnorm_ref(x0, x1, x2v);
            qx2[u] = pack2(x0, x0);
            qy2[u] = pack2(x1, x1);
            qz2[u] = pack2(x2v, x2v);
            q22[u] = pack2(s, s);
            best[u] = FLTMAX;
            gacc[u] = FLTMAX;
            jgrp[u] = 0.0f;
        }
    }
    __syncthreads();

    const ulonglong2* __restrict__ sp = (const ulonglong2*)sc;
    const int cand0 = b * NPTS + cblk * CT;

    for (int k8 = 0; k8 < CT / 2; k8 += 8) {
        // front-batch ALL candidate data for this unit (16 LDS.128 in flight)
        ulonglong2 c[16];
#pragma unroll
        for (int i = 0; i < 16; ++i) c[i] = sp[2 * k8 + i];

#pragma unroll
        for (int j = 0; j < 8; ++j) {
            const ulonglong2 A  = c[2 * j];      // (-2X pair, -2Y pair)
            const ulonglong2 Bv = c[2 * j + 1];  // (-2Z pair,  W pair)
            float cl, ch;
#pragma unroll
            for (int u = 0; u < UQ; ++u) {
                u64 t = fma2(qz2[u], Bv.x, fma2(qy2[u], A.y, mul2(qx2[u], A.x)));
                u64 d = add2(t, add2(q22[u], Bv.y));   // == fma(-2,xy,q2+c2)
                float dlo, dhi; unpack2(d, dlo, dhi);
                gacc[u] = fminf(gacc[u], fminf(dlo, dhi));
                if (u == 0) { cl = dlo; ch = dhi; }
                else        { cl = fminf(cl, dlo); ch = fminf(ch, dhi); }
            }
            colpart[w][j][lane] = pack2(cl, ch);
        }

        // row group commit (16 cands/group), ascending -> strict <
        const float gidx = (float)(cblk * (CT / GRPC) + (k8 >> 3));
#pragma unroll
        for (int u = 0; u < UQ; ++u) {
            jgrp[u] = (gacc[u] < best[u]) ? gidx : jgrp[u];
            best[u] = fminf(best[u], gacc[u]);
            gacc[u] = FLTMAX;
        }

        // col flush: 32 reductions (8 pairs x 2 query-halves x 2 cands);
        // each 64-query half stored as its own partial (ascending ranges)
        __syncwarp();
        {
            const int p = lane >> 2;          // pair 0..7
            const int s = (lane >> 1) & 1;    // query half (64 queries)
            const int h = lane & 1;           // lo/hi cand of the pair
            const float* fb = (const float*)colpart[w][p];
            float v = fb[(s * 16) * 2 + h];
#pragma unroll
            for (int i = 1; i < 16; ++i)
                v = fminf(v, fb[(s * 16 + i) * 2 + h]);
            g_col[qblk * 4 + w * 2 + s][cand0 + 2 * (k8 + p) + h] = v;
        }
        __syncwarp();
    }

    // row epilogue: stage to smem, write coalesced
#pragma unroll
    for (int u = 0; u < UQ; ++u)
        rowst[tid * UQ + u] = make_float2(best[u], jgrp[u]);
    __syncthreads();
    {
        const int base = b * NPTS + qblk * QT;
        float2* __restrict__ gr = &g_row[cblk][base];
        for (int i = tid; i < QT; i += BT) gr[i] = rowst[i];
    }
}

// Phase A: thread-per-element merge, fully coalesced. Ascending scan with
// strict < keeps the EARLIEST tying partial (exact first-occurrence).
__global__ __launch_bounds__(256) void nn_merge(float* __restrict__ out)
{
    const int t  = blockIdx.x * blockDim.x + threadIdx.x;   // [0, 2*BN)
    const int BN = BATCH * NPTS;

    if (t < BN) {
        const int qg = t;
        float2 r = g_row[0][qg];
        float bv = r.x, bg = r.y;
#pragma unroll
        for (int cb = 1; cb < NCB; ++cb) {
            const float2 rr = g_row[cb][qg];
            const bool tk = rr.x < bv;
            bv = tk ? rr.x : bv;
            bg = tk ? rr.y : bg;
        }
        out[qg] = bv;
        g_sel[0][qg] = (int)bg;
    } else {
        const int mg = t - BN;
        float bv = g_col[0][mg];
        int   bp = 0;
#pragma unroll 16
        for (int p = 1; p < NPART; ++p) {
            const float v = g_col[p][mg];
            const bool tk = v < bv;
            bv = tk ? v : bv;
            bp = tk ? p : bp;
        }
        out[BN + mg] = bv;
        g_sel[1][mg] = bp;
    }
}

// Phase B: warp-per-element rescan. Recomputes distances bit-identically in
// the winning group/range and takes the LOWEST matching global index.
__global__ __launch_bounds__(256) void nn_rescan(
    const float* __restrict__ xyz1,
    const float* __restrict__ xyz2,
    float* __restrict__ out)
{
    const int BN   = BATCH * NPTS;
    const int gw   = blockIdx.x * (blockDim.x >> 5) + (threadIdx.x >> 5);
    const int lane = threadIdx.x & 31;

    if (gw < BN) {
        // row: idx1 for query qg
        const int qg = gw;
        const int b  = qg >> 12;            // /NPTS
        const float bv = out[qg];
        const int base = g_sel[0][qg] * GRPC;

        const float* qp = xyz1 + 3 * qg;
        const float qx = qp[0], qy = qp[1], qz = qp[2];
        const float q2 = sqnorm_ref(qx, qy, qz);

        int found = 0x7fffffff;
        if (lane < GRPC) {
            const float* cp = xyz2 + (size_t)b * NPTS * 3 + 3 * (base + lane);
            const float c2 = sqnorm_ref(cp[0], cp[1], cp[2]);
            const float d = dist_ref(qx, qy, qz, q2, cp[0], cp[1], cp[2], c2);
            if (d == bv) found = base + lane;
        }
#pragma unroll
        for (int off = 16; off >= 1; off >>= 1)
            found = min(found, __shfl_xor_sync(0xffffffffu, found, off));

        if (lane == 0) out[2 * BN + qg] = (float)found;
    } else {
        // col: idx2 for candidate mg
        const int mg = gw - BN;
        const int b  = mg >> 12;
        const float bv = out[BN + mg];
        const int   bp = g_sel[1][mg];      // queries [bp*64, bp*64+64)

        const float* cp = xyz2 + 3 * mg;
        const float cx = cp[0], cy = cp[1], cz = cp[2];
        const float c2 = sqnorm_ref(cx, cy, cz);

        // rescan: lane l -> queries bp*64 + 2l + {0,1}, coalesced float2
        const int qn0 = b * NPTS + bp * QRNG + lane * 2;
        const float2* qv = (const float2*)(xyz1 + 3 * qn0);  // 8B aligned
        const float2 v0 = qv[0], v1 = qv[1], v2 = qv[2];
        const float qs[2][3] = {{v0.x, v0.y, v1.x}, {v1.y, v2.x, v2.y}};
        int found = 0x7fffffff;
#pragma unroll
        for (int k = 1; k >= 0; --k) {
            const float q2n = sqnorm_ref(qs[k][0], qs[k][1], qs[k][2]);
            const float d = dist_ref(qs[k][0], qs[k][1], qs[k][2], q2n,
                                     cx, cy, cz, c2);
            if (d == bv) found = bp * QRNG + lane * 2 + k;
        }
#pragma unroll
        for (int off = 16; off >= 1; off >>= 1)
            found = min(found, __shfl_xor_sync(0xffffffffu, found, off));

        if (lane == 0) out[3 * BN + mg] = (float)found;
    }
}

extern "C" void kernel_launch(void* const* d_in, const int* in_sizes, int n_in,
                              void* d_out, int out_size)
{
    (void)in_sizes; (void)n_in; (void)out_size;
    const float* xyz1 = (const float*)d_in[0];
    const float* xyz2 = (const float*)d_in[1];
    float* out = (float*)d_out;

    dim3 grid(NCB, NQB, BATCH);   // (16, 16, 16) = 4096 blocks
    nn_main<<<grid, BT>>>(xyz1, xyz2);

    const int BN = BATCH * NPTS;
    nn_merge<<<(2 * BN) / 256, 256>>>(out);
    nn_rescan<<<(2 * BN * 32) / 256, 256>>>(xyz1, xyz2, out);
}